// round 1
// baseline (speedup 1.0000x reference)
#include <cuda_runtime.h>
#include <math_constants.h>

#define TT 4096
#define NB 8
#define NEGF (-CUDART_INF_F)

// scratch for cross-block reduction (device globals: allowed, no allocation)
__device__ float    g_partial[NB];
__device__ unsigned g_ticket = 0;

__device__ __forceinline__ float pen(float yv, float idx, float eps) {
    return fmaxf(0.0f, fabsf(yv - idx) - eps);
}

__global__ void __launch_bounds__(256, 1)
custom_loss_kernel(const float* __restrict__ X,   // (8, 1, 4096)
                   const float* __restrict__ Y,   // (8, 2)
                   const unsigned* __restrict__ epsb,
                   float* __restrict__ out)       // scalar
{
    const int b    = blockIdx.x;
    const int tid  = threadIdx.x;
    const int w    = tid >> 5;
    const int lane = tid & 31;

    const float* x = X + b * TT;
    const float y0 = Y[2 * b + 0];
    const float y1 = Y[2 * b + 1];

    // eps may be int32 or float32; decode from bits. int 5 as float bits is a
    // denormal (~7e-45) << 1e-6, so the test is unambiguous.
    const unsigned eb = *epsb;
    const float    ef = __uint_as_float(eb);
    const float eps = (ef >= 1e-6f && ef <= 1e9f) ? ef : (float)(int)eb;

    // lane segment: 16 contiguous k-indices
    const int s = (w << 9) + (lane << 4);

    // x[s .. s+16) via 4x float4 (always aligned + in bounds)
    float xa[16];
#pragma unroll
    for (int q = 0; q < 4; q++) {
        float4 v = reinterpret_cast<const float4*>(x + s)[q];
        xa[4 * q + 0] = v.x; xa[4 * q + 1] = v.y;
        xa[4 * q + 2] = v.z; xa[4 * q + 3] = v.w;
    }
    // tail x[s+16 .. s+20] for the shifted-b values (guarded; OOB unused)
    float xt[5];
#pragma unroll
    for (int r = 0; r < 5; r++) {
        int ix = s + 16 + r;
        xt[r] = (ix < TT) ? __ldg(x + ix) : 0.0f;
    }

    // k-space scan (descending): a'[k] = a[k] masked k>=5 ; b'[k] = b[k+5]
    // P = max over i<=k in segment of a'[i] + b'[k]; A = max a'; Bm = max b'
    float P = NEGF, A = NEGF, suffB = NEGF;
#pragma unroll
    for (int t = 15; t >= 0; t--) {
        const int   k  = s + t;
        const int   j  = k + 5;
        const float xj = (t <= 10) ? xa[t + 5] : xt[t - 11];
        const float bv = (j < TT) ? (xj + 0.5f * pen(y1, (float)j, eps)) : NEGF;
        suffB = fmaxf(suffB, bv);
        const float av = (k >= 5) ? (xa[t] + 0.5f * pen(y0, (float)k, eps)) : NEGF;
        A = fmaxf(A, av);
        P = fmaxf(P, av + suffB);
    }
    float Bm = suffB;

    // ordered warp combine: lane l accumulates [l, l+off); left=this, right=l+off
#pragma unroll
    for (int off = 1; off < 32; off <<= 1) {
        float Pr = __shfl_down_sync(0xffffffffu, P,  off);
        float Ar = __shfl_down_sync(0xffffffffu, A,  off);
        float Br = __shfl_down_sync(0xffffffffu, Bm, off);
        if (lane + off < 32) {
            P  = fmaxf(fmaxf(P, Pr), A + Br);
            A  = fmaxf(A, Ar);
            Bm = fmaxf(Bm, Br);
        }
    }

    __shared__ float sP[8], sA[8], sB[8];
    if (lane == 0) { sP[w] = P; sA[w] = A; sB[w] = Bm; }
    __syncthreads();

    if (tid == 0) {
        float p = sP[0], a = sA[0];
#pragma unroll
        for (int q = 1; q < 8; q++) {
            p = fmaxf(fmaxf(p, sP[q]), a + sB[q]);
            a = fmaxf(a, sA[q]);
        }
        // init term uses UNMASKED a[1] + b[6]
        const float init = (x[1] + 0.5f * pen(y0, 1.0f, eps))
                         + (x[6] + 0.5f * pen(y1, 6.0f, eps));
        const float ob = fmaxf(p, init);

        g_partial[b] = ob;
        __threadfence();
        unsigned old = atomicAdd(&g_ticket, 1);
        if (old == NB - 1) {
            __threadfence();            // acquire: see all g_partial writes
            float ssum = 0.0f;
#pragma unroll
            for (int q = 0; q < NB; q++) ssum += g_partial[q];  // fixed order -> deterministic
            out[0] = ssum * (1.0f / NB);
            g_ticket = 0;               // re-arm for next replay
        }
    }
}

extern "C" void kernel_launch(void* const* d_in, const int* in_sizes, int n_in,
                              void* d_out, int out_size) {
    const float*    w_phi = (const float*)d_in[0];
    const float*    y     = (const float*)d_in[1];
    const unsigned* epsb  = (const unsigned*)d_in[2];
    float*          out   = (float*)d_out;
    custom_loss_kernel<<<NB, 256>>>(w_phi, y, epsb, out);
}